// round 12
// baseline (speedup 1.0000x reference)
#include <cuda_runtime.h>
#include <cuda_bf16.h>
#include <mma.h>

using namespace nvcuda;

#define N_NODES 100000
#define N_PAD   100096                    // 128-aligned for unguarded wmma stores
#define N_EDGES 800000
#define DIM     64
#define HEADS   4
#define NBLK    ((N_NODES + 255) / 256)   // 391 scan blocks

typedef unsigned long long u64;
typedef unsigned int       u32;

// L2-resident scratch (GB300 L2 ~126MB; Q+K+V = 76.9MB)
__device__ float g_Q[N_PAD * DIM];
__device__ float g_K[N_PAD * DIM];
__device__ float g_V[N_PAD * DIM];

// Pre-converted weights: [m][n][k] bf16, hi and lo split (W^T layout)
__device__ __nv_bfloat16 g_Wbh[3 * 64 * 64];
__device__ __nv_bfloat16 g_Wbl[3 * 64 * 64];

// CSR scratch
__device__ int g_deg[N_NODES];
__device__ int g_start[N_NODES];
__device__ int g_cursor[N_NODES];
__device__ int g_incl[NBLK * 256];
__device__ int g_bsum[NBLK];
__device__ int g_btop[NBLK];
__device__ int g_colS[N_EDGES];
__device__ int g_perm[N_EDGES];

// ---------------------------------------------------------------------------
// One-shot W transpose + bf16 hi/lo split. 12288 elements.
// ---------------------------------------------------------------------------
__global__ void wconv(const float* __restrict__ Wq, const float* __restrict__ Wk,
                      const float* __restrict__ Wv) {
    int idx = blockIdx.x * 256 + threadIdx.x;
    if (idx >= 3 * 4096) return;
    int m = idx >> 12, rem = idx & 4095;
    int n = rem >> 6, k = rem & 63;
    const float* W = (m == 0) ? Wq : (m == 1) ? Wk : Wv;
    float x = W[k * 64 + n];
    __nv_bfloat16 h = __float2bfloat16_rn(x);
    __nv_bfloat16 l = __float2bfloat16_rn(x - __bfloat162float(h));
    g_Wbh[idx] = h;
    g_Wbl[idx] = l;
}

// ---------------------------------------------------------------------------
// Tensor-core QKV GEMM via wmma (bf16 two-term split, err ~2^-18).
// 256 threads (8 warps), 128-node tile. A fragments register-resident and
// reused across all 3 weight matrices; B fragments loaded straight from the
// pre-converted L2-hot global arrays. One __syncthreads total.
// ---------------------------------------------------------------------------
#define AS 72

__global__ __launch_bounds__(256, 2) void gemm_qkv_wmma(const float* __restrict__ E)
{
    extern __shared__ __nv_bfloat16 sb[];
    __nv_bfloat16* Ah = sb;                    // [128][AS]
    __nv_bfloat16* Al = Ah + 128 * AS;

    int t    = threadIdx.x;
    int w    = t >> 5;
    int base = blockIdx.x * 128;

    // --- A tile: each thread converts half a row (32 floats) ---
    {
        int r    = t >> 1;
        int coff = (t & 1) * 32;
        int node = base + r;
        const float2* src = (const float2*)(E + (size_t)node * 64 + coff);
        __nv_bfloat16* dh = Ah + r * AS + coff;
        __nv_bfloat16* dl = Al + r * AS + coff;
        if (node < N_NODES) {
            #pragma unroll
            for (int i = 0; i < 16; i++) {
                float2 x = src[i];
                __nv_bfloat162 h = __float22bfloat162_rn(x);
                float2 hf = __bfloat1622float2(h);
                __nv_bfloat162 l = __float22bfloat162_rn(
                    make_float2(x.x - hf.x, x.y - hf.y));
                *(__nv_bfloat162*)(dh + 2 * i) = h;
                *(__nv_bfloat162*)(dl + 2 * i) = l;
            }
        } else {
            #pragma unroll
            for (int i = 0; i < 16; i++) {
                *(__nv_bfloat162*)(dh + 2 * i) = __nv_bfloat162(0.f, 0.f);
                *(__nv_bfloat162*)(dl + 2 * i) = __nv_bfloat162(0.f, 0.f);
            }
        }
    }
    __syncthreads();

    // --- A fragments: load once, reuse for all 3 matrices ---
    wmma::fragment<wmma::matrix_a, 16, 16, 16, __nv_bfloat16, wmma::row_major>
        ah[4], al[4];
    #pragma unroll
    for (int k = 0; k < 4; k++) {
        wmma::load_matrix_sync(ah[k], Ah + (w * 16) * AS + k * 16, AS);
        wmma::load_matrix_sync(al[k], Al + (w * 16) * AS + k * 16, AS);
    }

    #pragma unroll
    for (int m = 0; m < 3; m++) {
        const __nv_bfloat16* BH = g_Wbh + m * 4096;   // [n][k], col_major frag
        const __nv_bfloat16* BL = g_Wbl + m * 4096;

        wmma::fragment<wmma::accumulator, 16, 16, 16, float> acc[4];
        #pragma unroll
        for (int n = 0; n < 4; n++) wmma::fill_fragment(acc[n], 0.0f);

        #pragma unroll
        for (int k = 0; k < 4; k++) {
            #pragma unroll
            for (int n = 0; n < 4; n++) {
                wmma::fragment<wmma::matrix_b, 16, 16, 16, __nv_bfloat16,
                               wmma::col_major> bh, bl;
                wmma::load_matrix_sync(bh, BH + (n * 16) * 64 + k * 16, 64);
                wmma::load_matrix_sync(bl, BL + (n * 16) * 64 + k * 16, 64);
                wmma::mma_sync(acc[n], ah[k], bh, acc[n]);
                wmma::mma_sync(acc[n], ah[k], bl, acc[n]);
                wmma::mma_sync(acc[n], al[k], bh, acc[n]);
            }
        }

        float* O = (m == 0) ? g_Q : (m == 1) ? g_K : g_V;
        #pragma unroll
        for (int n = 0; n < 4; n++)
            wmma::store_matrix_sync(O + (size_t)(base + w * 16) * 64 + n * 16,
                                    acc[n], 64, wmma::mem_row_major);
    }
}

#define SMEM_WMMA (2 * 128 * AS * (int)sizeof(__nv_bfloat16))   // 36864

// ---------------------------------------------------------------------------
// CSR build: histogram -> block scan -> top scan -> fix+cursor -> scatter.
// ---------------------------------------------------------------------------
__global__ void hist_kernel(const int* __restrict__ rows) {
    int e = blockIdx.x * blockDim.x + threadIdx.x;
    if (e < N_EDGES) atomicAdd(&g_deg[rows[e]], 1);
}

__global__ void scan_blocks() {
    int i    = blockIdx.x * 256 + threadIdx.x;
    int lane = threadIdx.x & 31, wid = threadIdx.x >> 5;
    int v = (i < N_NODES) ? g_deg[i] : 0;
    #pragma unroll
    for (int o = 1; o < 32; o <<= 1) {
        int u = __shfl_up_sync(0xffffffffu, v, o);
        if (lane >= o) v += u;
    }
    __shared__ int ws[8];
    if (lane == 31) ws[wid] = v;
    __syncthreads();
    if (wid == 0 && lane < 8) {
        int x = ws[lane];
        #pragma unroll
        for (int o = 1; o < 8; o <<= 1) {
            int u = __shfl_up_sync(0xffu, x, o);
            if (lane >= o) x += u;
        }
        ws[lane] = x;
    }
    __syncthreads();
    if (wid > 0) v += ws[wid - 1];
    g_incl[blockIdx.x * 256 + threadIdx.x] = v;
    if (threadIdx.x == 255) g_bsum[blockIdx.x] = v;
}

__global__ void scan_top() {
    int t    = threadIdx.x;
    int lane = t & 31, wid = t >> 5;
    int v = (t < NBLK) ? g_bsum[t] : 0;
    #pragma unroll
    for (int o = 1; o < 32; o <<= 1) {
        int u = __shfl_up_sync(0xffffffffu, v, o);
        if (lane >= o) v += u;
    }
    __shared__ int ws[16];
    if (lane == 31) ws[wid] = v;
    __syncthreads();
    if (wid == 0 && lane < 16) {
        int x = ws[lane];
        #pragma unroll
        for (int o = 1; o < 16; o <<= 1) {
            int u = __shfl_up_sync(0xffffu, x, o);
            if (lane >= o) x += u;
        }
        ws[lane] = x;
    }
    __syncthreads();
    if (wid > 0) v += ws[wid - 1];
    if (t < NBLK) g_btop[t] = v;
}

__global__ void scan_fix() {
    int i = blockIdx.x * 256 + threadIdx.x;
    if (i >= N_NODES) return;
    int boff = (blockIdx.x > 0) ? g_btop[blockIdx.x - 1] : 0;
    int st = g_incl[i] + boff - g_deg[i];
    g_start[i]  = st;
    g_cursor[i] = st;
}

__global__ void scatter_kernel(const int* __restrict__ rows,
                               const int* __restrict__ cols) {
    int e = blockIdx.x * blockDim.x + threadIdx.x;
    if (e >= N_EDGES) return;
    int r = rows[e];
    int p = atomicAdd(&g_cursor[r], 1);
    g_colS[p] = cols[e];
    g_perm[p] = e;
}

// ---------------------------------------------------------------------------
// Warp-per-node fused attention (R9 best). Lane l owns dims [2l, 2l+1].
// ---------------------------------------------------------------------------
__device__ __forceinline__ float edge_ex(float2 q2, int c, int lane, float2& v2) {
    float2 k2 = *(const float2*)&g_K[c * DIM + lane * 2];
    v2        = *(const float2*)&g_V[c * DIM + lane * 2];
    float p = q2.x * k2.x + q2.y * k2.y;
    p += __shfl_xor_sync(0xffffffffu, p, 1);
    p += __shfl_xor_sync(0xffffffffu, p, 2);
    p += __shfl_xor_sync(0xffffffffu, p, 4);
    p = fminf(fmaxf(p, -10.0f), 10.0f);
    return __expf(p);
}

__global__ __launch_bounds__(256) void node_attn(float* __restrict__ res,
                                                 float* __restrict__ att) {
    int gwarp = (blockIdx.x * blockDim.x + threadIdx.x) >> 5;
    if (gwarp >= N_NODES) return;
    int lane = threadIdx.x & 31;
    int n = gwarp;
    int s = g_start[n];
    int d = g_deg[n];
    int end = s + d;

    float2 q2 = *(const float2*)&g_Q[n * DIM + lane * 2];
    float acc0 = 0.f, acc1 = 0.f, norm = 0.f;
    int h = lane >> 3;
    bool leader = (lane & 7) == 0;

    int j = s;
    for (; j + 3 < end; j += 4) {
        int c0 = g_colS[j],     c1 = g_colS[j + 1];
        int c2 = g_colS[j + 2], c3 = g_colS[j + 3];
        int e0 = g_perm[j],     e1 = g_perm[j + 1];
        int e2 = g_perm[j + 2], e3 = g_perm[j + 3];
        float2 v0, v1, v2, v3;
        float ex0 = edge_ex(q2, c0, lane, v0);
        float ex1 = edge_ex(q2, c1, lane, v1);
        float ex2 = edge_ex(q2, c2, lane, v2);
        float ex3 = edge_ex(q2, c3, lane, v3);
        norm += (ex0 + ex1) + (ex2 + ex3);
        acc0 = fmaf(ex0, v0.x, acc0); acc0 = fmaf(ex1, v1.x, acc0);
        acc0 = fmaf(ex2, v2.x, acc0); acc0 = fmaf(ex3, v3.x, acc0);
        acc1 = fmaf(ex0, v0.y, acc1); acc1 = fmaf(ex1, v1.y, acc1);
        acc1 = fmaf(ex2, v2.y, acc1); acc1 = fmaf(ex3, v3.y, acc1);
        if (leader) {
            att[e0 * 4 + h] = ex0;
            att[e1 * 4 + h] = ex1;
            att[e2 * 4 + h] = ex2;
            att[e3 * 4 + h] = ex3;
        }
    }
    for (; j < end; j++) {
        int c0 = g_colS[j], e0 = g_perm[j];
        float2 v0;
        float ex0 = edge_ex(q2, c0, lane, v0);
        norm += ex0;
        acc0 = fmaf(ex0, v0.x, acc0);
        acc1 = fmaf(ex0, v0.y, acc1);
        if (leader) att[e0 * 4 + h] = ex0;
    }

    float inv = 1.0f / (norm + 1e-8f);
    float2 r2 = make_float2(acc0 * inv, acc1 * inv);
    *(float2*)&res[n * DIM + lane * 2] = r2;

    __syncwarp();
    float i0 = __shfl_sync(0xffffffffu, inv, 0);
    float i1 = __shfl_sync(0xffffffffu, inv, 8);
    float i2 = __shfl_sync(0xffffffffu, inv, 16);
    float i3 = __shfl_sync(0xffffffffu, inv, 24);
    for (int jj = s + lane; jj < end; jj += 32) {
        int e = g_perm[jj];
        float4 a = *(float4*)&att[e * 4];
        a.x *= i0; a.y *= i1; a.z *= i2; a.w *= i3;
        *(float4*)&att[e * 4] = a;
    }
}

// ---------------------------------------------------------------------------
extern "C" void kernel_launch(void* const* d_in, const int* in_sizes, int n_in,
                              void* d_out, int out_size) {
    const float* embeds = (const float*)d_in[0];
    const float* Wq     = (const float*)d_in[1];
    const float* Wk     = (const float*)d_in[2];
    const float* Wv     = (const float*)d_in[3];
    const int*   rows   = (const int*)d_in[4];
    const int*   cols   = (const int*)d_in[5];

    float* res = (float*)d_out;                    // [N_NODES, 64]
    float* att = (float*)d_out + N_NODES * DIM;    // [N_EDGES, 4]

    static cudaStream_t sCsr = nullptr;
    static cudaEvent_t  evFork = nullptr, evJoin = nullptr;
    if (sCsr == nullptr) {
        cudaStreamCreateWithFlags(&sCsr, cudaStreamNonBlocking);
        cudaEventCreateWithFlags(&evFork, cudaEventDisableTiming);
        cudaEventCreateWithFlags(&evJoin, cudaEventDisableTiming);
    }

    void* pDeg;
    cudaGetSymbolAddress(&pDeg, g_deg);

    // Fork: CSR chain (rows/cols only) parallel to tensor-core GEMM.
    cudaEventRecord(evFork, 0);
    cudaStreamWaitEvent(sCsr, evFork, 0);

    // Branch A (stream 0): W pre-convert + wmma QKV projection
    wconv<<<48, 256>>>(Wq, Wk, Wv);
    cudaFuncSetAttribute(gemm_qkv_wmma,
                         cudaFuncAttributeMaxDynamicSharedMemorySize, SMEM_WMMA);
    gemm_qkv_wmma<<<(N_NODES + 127) / 128, 256, SMEM_WMMA>>>(embeds);

    // Branch B (sCsr): CSR build
    int eb = (N_EDGES + 255) / 256;
    cudaMemsetAsync(pDeg, 0, (size_t)N_NODES * sizeof(int), sCsr);
    hist_kernel<<<eb, 256, 0, sCsr>>>(rows);
    scan_blocks<<<NBLK, 256, 0, sCsr>>>();
    scan_top<<<1, 512, 0, sCsr>>>();
    scan_fix<<<NBLK, 256, 0, sCsr>>>();
    scatter_kernel<<<eb, 256, 0, sCsr>>>(rows, cols);

    // Join
    cudaEventRecord(evJoin, sCsr);
    cudaStreamWaitEvent(0, evJoin, 0);

    // fused attention: logits + softmax + aggregate + att normalize
    int nb = (N_NODES * 32 + 255) / 256;
    node_attn<<<nb, 256>>>(res, att);
}

// round 13
// speedup vs baseline: 1.4283x; 1.4283x over previous
#include <cuda_runtime.h>
#include <cuda_bf16.h>
#include <mma.h>

using namespace nvcuda;

#define N_NODES 100000
#define N_PAD   100096                    // 128-aligned for unguarded wmma stores
#define N_EDGES 800000
#define DIM     64
#define HEADS   4
#define NBLK    ((N_NODES + 255) / 256)   // 391 scan blocks

typedef unsigned long long u64;
typedef unsigned int       u32;

// L2-resident scratch (GB300 L2 ~126MB; Q+K+V = 76.9MB)
__device__ float g_Q[N_PAD * DIM];
__device__ float g_K[N_PAD * DIM];
__device__ float g_V[N_PAD * DIM];

// Pre-converted weights: [m][n][k] bf16 (W^T layout), hi / lo split
__device__ __nv_bfloat16 g_Wbh[3 * 64 * 64];
__device__ __nv_bfloat16 g_Wbl[3 * 64 * 64];

// CSR scratch
__device__ int g_deg[N_NODES];
__device__ int g_start[N_NODES];
__device__ int g_cursor[N_NODES];
__device__ int g_incl[NBLK * 256];
__device__ int g_bsum[NBLK];
__device__ int g_btop[NBLK];
__device__ int g_colS[N_EDGES];
__device__ int g_perm[N_EDGES];

// ---------------------------------------------------------------------------
// One-shot W transpose + bf16 hi/lo split. 12288 elements.
// ---------------------------------------------------------------------------
__global__ void wconv(const float* __restrict__ Wq, const float* __restrict__ Wk,
                      const float* __restrict__ Wv) {
    int idx = blockIdx.x * 256 + threadIdx.x;
    if (idx >= 3 * 4096) return;
    int m = idx >> 12, rem = idx & 4095;
    int n = rem >> 6, k = rem & 63;
    const float* W = (m == 0) ? Wq : (m == 1) ? Wk : Wv;
    float x = W[k * 64 + n];
    __nv_bfloat16 h = __float2bfloat16_rn(x);
    __nv_bfloat16 l = __float2bfloat16_rn(x - __bfloat162float(h));
    g_Wbh[idx] = h;
    g_Wbl[idx] = l;
}

// ---------------------------------------------------------------------------
// Tensor-core QKV GEMM via wmma (bf16 two-term split, err ~2^-18).
// 256 threads (8 warps), 128-node tile. All three pre-converted B matrices
// staged into smem ONCE with uint4 copies; A fragments register-resident
// across the m-loop; one __syncthreads total.
// ---------------------------------------------------------------------------
#define AS 72
#define BS 72

__global__ __launch_bounds__(256, 2) void gemm_qkv_wmma(const float* __restrict__ E)
{
    extern __shared__ __nv_bfloat16 sb[];
    __nv_bfloat16* Ah = sb;                    // [128][AS]
    __nv_bfloat16* Al = Ah + 128 * AS;
    __nv_bfloat16* Bh = Al + 128 * AS;         // [3][64][BS]
    __nv_bfloat16* Bl = Bh + 3 * 64 * BS;

    int t    = threadIdx.x;
    int w    = t >> 5;
    int base = blockIdx.x * 128;

    // --- A tile: each thread converts half a row (32 floats) ---
    {
        int r    = t >> 1;
        int coff = (t & 1) * 32;
        int node = base + r;
        const float2* src = (const float2*)(E + (size_t)node * 64 + coff);
        __nv_bfloat16* dh = Ah + r * AS + coff;
        __nv_bfloat16* dl = Al + r * AS + coff;
        if (node < N_NODES) {
            #pragma unroll
            for (int i = 0; i < 16; i++) {
                float2 x = src[i];
                __nv_bfloat162 h = __float22bfloat162_rn(x);
                float2 hf = __bfloat1622float2(h);
                __nv_bfloat162 l = __float22bfloat162_rn(
                    make_float2(x.x - hf.x, x.y - hf.y));
                *(__nv_bfloat162*)(dh + 2 * i) = h;
                *(__nv_bfloat162*)(dl + 2 * i) = l;
            }
        } else {
            #pragma unroll
            for (int i = 0; i < 16; i++) {
                *(__nv_bfloat162*)(dh + 2 * i) = __nv_bfloat162(0.f, 0.f);
                *(__nv_bfloat162*)(dl + 2 * i) = __nv_bfloat162(0.f, 0.f);
            }
        }
    }

    // --- B tiles: vectorized copy of pre-converted weights (no converts) ---
    // v in [0, 1536): 8 bf16 per uint4. global g = m*4096 + n*64 + k8*8.
    for (int v = t; v < 1536; v += 256) {
        int m  = v >> 9;
        int rm = v & 511;
        int n  = rm >> 3;
        int k8 = rm & 7;
        int soff = m * 64 * BS + n * BS + k8 * 8;
        *(uint4*)(Bh + soff) = ((const uint4*)g_Wbh)[v];
        *(uint4*)(Bl + soff) = ((const uint4*)g_Wbl)[v];
    }
    __syncthreads();

    // --- A fragments: load once, reuse for all 3 matrices ---
    wmma::fragment<wmma::matrix_a, 16, 16, 16, __nv_bfloat16, wmma::row_major>
        ah[4], al[4];
    #pragma unroll
    for (int k = 0; k < 4; k++) {
        wmma::load_matrix_sync(ah[k], Ah + (w * 16) * AS + k * 16, AS);
        wmma::load_matrix_sync(al[k], Al + (w * 16) * AS + k * 16, AS);
    }

    #pragma unroll
    for (int m = 0; m < 3; m++) {
        const __nv_bfloat16* BH = Bh + m * 64 * BS;
        const __nv_bfloat16* BL = Bl + m * 64 * BS;

        wmma::fragment<wmma::accumulator, 16, 16, 16, float> acc[4];
        #pragma unroll
        for (int n = 0; n < 4; n++) wmma::fill_fragment(acc[n], 0.0f);

        #pragma unroll
        for (int k = 0; k < 4; k++) {
            #pragma unroll
            for (int n = 0; n < 4; n++) {
                wmma::fragment<wmma::matrix_b, 16, 16, 16, __nv_bfloat16,
                               wmma::col_major> bh, bl;
                wmma::load_matrix_sync(bh, BH + (n * 16) * BS + k * 16, BS);
                wmma::load_matrix_sync(bl, BL + (n * 16) * BS + k * 16, BS);
                wmma::mma_sync(acc[n], ah[k], bh, acc[n]);
                wmma::mma_sync(acc[n], ah[k], bl, acc[n]);
                wmma::mma_sync(acc[n], al[k], bh, acc[n]);
            }
        }

        float* O = (m == 0) ? g_Q : (m == 1) ? g_K : g_V;
        #pragma unroll
        for (int n = 0; n < 4; n++)
            wmma::store_matrix_sync(O + (size_t)(base + w * 16) * 64 + n * 16,
                                    acc[n], 64, wmma::mem_row_major);
    }
}

#define SMEM_WMMA ((2 * 128 * AS + 2 * 3 * 64 * BS) * (int)sizeof(__nv_bfloat16))

// ---------------------------------------------------------------------------
// CSR build: histogram -> block scan -> top scan -> fix+cursor -> scatter.
// ---------------------------------------------------------------------------
__global__ void hist_kernel(const int* __restrict__ rows) {
    int e = blockIdx.x * blockDim.x + threadIdx.x;
    if (e < N_EDGES) atomicAdd(&g_deg[rows[e]], 1);
}

__global__ void scan_blocks() {
    int i    = blockIdx.x * 256 + threadIdx.x;
    int lane = threadIdx.x & 31, wid = threadIdx.x >> 5;
    int v = (i < N_NODES) ? g_deg[i] : 0;
    #pragma unroll
    for (int o = 1; o < 32; o <<= 1) {
        int u = __shfl_up_sync(0xffffffffu, v, o);
        if (lane >= o) v += u;
    }
    __shared__ int ws[8];
    if (lane == 31) ws[wid] = v;
    __syncthreads();
    if (wid == 0 && lane < 8) {
        int x = ws[lane];
        #pragma unroll
        for (int o = 1; o < 8; o <<= 1) {
            int u = __shfl_up_sync(0xffu, x, o);
            if (lane >= o) x += u;
        }
        ws[lane] = x;
    }
    __syncthreads();
    if (wid > 0) v += ws[wid - 1];
    g_incl[blockIdx.x * 256 + threadIdx.x] = v;
    if (threadIdx.x == 255) g_bsum[blockIdx.x] = v;
}

__global__ void scan_top() {
    int t    = threadIdx.x;
    int lane = t & 31, wid = t >> 5;
    int v = (t < NBLK) ? g_bsum[t] : 0;
    #pragma unroll
    for (int o = 1; o < 32; o <<= 1) {
        int u = __shfl_up_sync(0xffffffffu, v, o);
        if (lane >= o) v += u;
    }
    __shared__ int ws[16];
    if (lane == 31) ws[wid] = v;
    __syncthreads();
    if (wid == 0 && lane < 16) {
        int x = ws[lane];
        #pragma unroll
        for (int o = 1; o < 16; o <<= 1) {
            int u = __shfl_up_sync(0xffffu, x, o);
            if (lane >= o) x += u;
        }
        ws[lane] = x;
    }
    __syncthreads();
    if (wid > 0) v += ws[wid - 1];
    if (t < NBLK) g_btop[t] = v;
}

__global__ void scan_fix() {
    int i = blockIdx.x * 256 + threadIdx.x;
    if (i >= N_NODES) return;
    int boff = (blockIdx.x > 0) ? g_btop[blockIdx.x - 1] : 0;
    int st = g_incl[i] + boff - g_deg[i];
    g_start[i]  = st;
    g_cursor[i] = st;
}

__global__ void scatter_kernel(const int* __restrict__ rows,
                               const int* __restrict__ cols) {
    int e = blockIdx.x * blockDim.x + threadIdx.x;
    if (e >= N_EDGES) return;
    int r = rows[e];
    int p = atomicAdd(&g_cursor[r], 1);
    g_colS[p] = cols[e];
    g_perm[p] = e;
}

// ---------------------------------------------------------------------------
// Warp-per-node fused attention. 64-thread blocks (2 warps) to shrink the
// intra-block degree-imbalance tax. Lane l owns dims [2l, 2l+1].
// ---------------------------------------------------------------------------
__device__ __forceinline__ float edge_ex(float2 q2, int c, int lane, float2& v2) {
    float2 k2 = *(const float2*)&g_K[c * DIM + lane * 2];
    v2        = *(const float2*)&g_V[c * DIM + lane * 2];
    float p = q2.x * k2.x + q2.y * k2.y;
    p += __shfl_xor_sync(0xffffffffu, p, 1);
    p += __shfl_xor_sync(0xffffffffu, p, 2);
    p += __shfl_xor_sync(0xffffffffu, p, 4);
    p = fminf(fmaxf(p, -10.0f), 10.0f);
    return __expf(p);
}

__global__ __launch_bounds__(64) void node_attn(float* __restrict__ res,
                                                float* __restrict__ att) {
    int gwarp = blockIdx.x * 2 + (threadIdx.x >> 5);
    if (gwarp >= N_NODES) return;
    int lane = threadIdx.x & 31;
    int n = gwarp;
    int s = g_start[n];
    int d = g_deg[n];
    int end = s + d;

    float2 q2 = *(const float2*)&g_Q[n * DIM + lane * 2];
    float acc0 = 0.f, acc1 = 0.f, norm = 0.f;
    int h = lane >> 3;
    bool leader = (lane & 7) == 0;

    int j = s;
    for (; j + 3 < end; j += 4) {
        int c0 = g_colS[j],     c1 = g_colS[j + 1];
        int c2 = g_colS[j + 2], c3 = g_colS[j + 3];
        int e0 = g_perm[j],     e1 = g_perm[j + 1];
        int e2 = g_perm[j + 2], e3 = g_perm[j + 3];
        float2 v0, v1, v2, v3;
        float ex0 = edge_ex(q2, c0, lane, v0);
        float ex1 = edge_ex(q2, c1, lane, v1);
        float ex2 = edge_ex(q2, c2, lane, v2);
        float ex3 = edge_ex(q2, c3, lane, v3);
        norm += (ex0 + ex1) + (ex2 + ex3);
        acc0 = fmaf(ex0, v0.x, acc0); acc0 = fmaf(ex1, v1.x, acc0);
        acc0 = fmaf(ex2, v2.x, acc0); acc0 = fmaf(ex3, v3.x, acc0);
        acc1 = fmaf(ex0, v0.y, acc1); acc1 = fmaf(ex1, v1.y, acc1);
        acc1 = fmaf(ex2, v2.y, acc1); acc1 = fmaf(ex3, v3.y, acc1);
        if (leader) {
            att[e0 * 4 + h] = ex0;
            att[e1 * 4 + h] = ex1;
            att[e2 * 4 + h] = ex2;
            att[e3 * 4 + h] = ex3;
        }
    }
    for (; j < end; j++) {
        int c0 = g_colS[j], e0 = g_perm[j];
        float2 v0;
        float ex0 = edge_ex(q2, c0, lane, v0);
        norm += ex0;
        acc0 = fmaf(ex0, v0.x, acc0);
        acc1 = fmaf(ex0, v0.y, acc1);
        if (leader) att[e0 * 4 + h] = ex0;
    }

    float inv = 1.0f / (norm + 1e-8f);
    float2 r2 = make_float2(acc0 * inv, acc1 * inv);
    *(float2*)&res[n * DIM + lane * 2] = r2;

    __syncwarp();
    float i0 = __shfl_sync(0xffffffffu, inv, 0);
    float i1 = __shfl_sync(0xffffffffu, inv, 8);
    float i2 = __shfl_sync(0xffffffffu, inv, 16);
    float i3 = __shfl_sync(0xffffffffu, inv, 24);
    for (int jj = s + lane; jj < end; jj += 32) {
        int e = g_perm[jj];
        float4 a = *(float4*)&att[e * 4];
        a.x *= i0; a.y *= i1; a.z *= i2; a.w *= i3;
        *(float4*)&att[e * 4] = a;
    }
}

// ---------------------------------------------------------------------------
extern "C" void kernel_launch(void* const* d_in, const int* in_sizes, int n_in,
                              void* d_out, int out_size) {
    const float* embeds = (const float*)d_in[0];
    const float* Wq     = (const float*)d_in[1];
    const float* Wk     = (const float*)d_in[2];
    const float* Wv     = (const float*)d_in[3];
    const int*   rows   = (const int*)d_in[4];
    const int*   cols   = (const int*)d_in[5];

    float* res = (float*)d_out;                    // [N_NODES, 64]
    float* att = (float*)d_out + N_NODES * DIM;    // [N_EDGES, 4]

    static cudaStream_t sCsr = nullptr;
    static cudaEvent_t  evFork = nullptr, evJoin = nullptr;
    if (sCsr == nullptr) {
        cudaStreamCreateWithFlags(&sCsr, cudaStreamNonBlocking);
        cudaEventCreateWithFlags(&evFork, cudaEventDisableTiming);
        cudaEventCreateWithFlags(&evJoin, cudaEventDisableTiming);
    }

    void* pDeg;
    cudaGetSymbolAddress(&pDeg, g_deg);

    // Fork: CSR chain (rows/cols only) parallel to tensor-core GEMM.
    cudaEventRecord(evFork, 0);
    cudaStreamWaitEvent(sCsr, evFork, 0);

    // Branch A (stream 0): W pre-convert + wmma QKV projection
    wconv<<<48, 256>>>(Wq, Wk, Wv);
    cudaFuncSetAttribute(gemm_qkv_wmma,
                         cudaFuncAttributeMaxDynamicSharedMemorySize, SMEM_WMMA);
    gemm_qkv_wmma<<<(N_NODES + 127) / 128, 256, SMEM_WMMA>>>(embeds);

    // Branch B (sCsr): CSR build
    int eb = (N_EDGES + 255) / 256;
    cudaMemsetAsync(pDeg, 0, (size_t)N_NODES * sizeof(int), sCsr);
    hist_kernel<<<eb, 256, 0, sCsr>>>(rows);
    scan_blocks<<<NBLK, 256, 0, sCsr>>>();
    scan_top<<<1, 512, 0, sCsr>>>();
    scan_fix<<<NBLK, 256, 0, sCsr>>>();
    scatter_kernel<<<eb, 256, 0, sCsr>>>(rows, cols);

    // Join
    cudaEventRecord(evJoin, sCsr);
    cudaStreamWaitEvent(0, evJoin, 0);

    // fused attention: logits + softmax + aggregate + att normalize
    node_attn<<<(N_NODES + 1) / 2, 64>>>(res, att);
}

// round 14
// speedup vs baseline: 1.4374x; 1.0063x over previous
#include <cuda_runtime.h>
#include <cuda_bf16.h>
#include <mma.h>

using namespace nvcuda;

#define N_NODES 100000
#define N_PAD   100096                    // 128-aligned for unguarded wmma stores
#define N_EDGES 800000
#define DIM     64
#define HEADS   4
#define NBLK    ((N_NODES + 255) / 256)   // 391 scan blocks

typedef unsigned long long u64;
typedef unsigned int       u32;

// L2-resident scratch (GB300 L2 ~126MB; Q+K+V = 76.9MB)
__device__ float g_Q[N_PAD * DIM];
__device__ float g_K[N_PAD * DIM];
__device__ float g_V[N_PAD * DIM];

// Pre-converted weights: [m][n][k] bf16 (W^T layout), hi / lo split
__device__ __nv_bfloat16 g_Wbh[3 * 64 * 64];
__device__ __nv_bfloat16 g_Wbl[3 * 64 * 64];

// CSR scratch
__device__ int g_deg[N_NODES];
__device__ int g_start[N_NODES];
__device__ int g_cursor[N_NODES];
__device__ int g_incl[NBLK * 256];
__device__ int g_bsum[NBLK];
__device__ int g_colS[N_EDGES];
__device__ int g_perm[N_EDGES];

// ---------------------------------------------------------------------------
// One-shot W transpose + bf16 hi/lo split. 12288 elements.
// ---------------------------------------------------------------------------
__global__ void wconv(const float* __restrict__ Wq, const float* __restrict__ Wk,
                      const float* __restrict__ Wv) {
    int idx = blockIdx.x * 256 + threadIdx.x;
    if (idx >= 3 * 4096) return;
    int m = idx >> 12, rem = idx & 4095;
    int n = rem >> 6, k = rem & 63;
    const float* W = (m == 0) ? Wq : (m == 1) ? Wk : Wv;
    float x = W[k * 64 + n];
    __nv_bfloat16 h = __float2bfloat16_rn(x);
    __nv_bfloat16 l = __float2bfloat16_rn(x - __bfloat162float(h));
    g_Wbh[idx] = h;
    g_Wbl[idx] = l;
}

// ---------------------------------------------------------------------------
// Tensor-core QKV GEMM via wmma (bf16 two-term split, err ~2^-18).
// 256 threads (8 warps), 128-node tile. Pre-converted B matrices staged once
// with uint4 copies; A fragments register-resident; one __syncthreads.
// ---------------------------------------------------------------------------
#define AS 72
#define BS 72

__global__ __launch_bounds__(256, 2) void gemm_qkv_wmma(const float* __restrict__ E)
{
    extern __shared__ __nv_bfloat16 sb[];
    __nv_bfloat16* Ah = sb;                    // [128][AS]
    __nv_bfloat16* Al = Ah + 128 * AS;
    __nv_bfloat16* Bh = Al + 128 * AS;         // [3][64][BS]
    __nv_bfloat16* Bl = Bh + 3 * 64 * BS;

    int t    = threadIdx.x;
    int w    = t >> 5;
    int base = blockIdx.x * 128;

    // --- A tile: each thread converts half a row (32 floats) ---
    {
        int r    = t >> 1;
        int coff = (t & 1) * 32;
        int node = base + r;
        const float2* src = (const float2*)(E + (size_t)node * 64 + coff);
        __nv_bfloat16* dh = Ah + r * AS + coff;
        __nv_bfloat16* dl = Al + r * AS + coff;
        if (node < N_NODES) {
            #pragma unroll
            for (int i = 0; i < 16; i++) {
                float2 x = src[i];
                __nv_bfloat162 h = __float22bfloat162_rn(x);
                float2 hf = __bfloat1622float2(h);
                __nv_bfloat162 l = __float22bfloat162_rn(
                    make_float2(x.x - hf.x, x.y - hf.y));
                *(__nv_bfloat162*)(dh + 2 * i) = h;
                *(__nv_bfloat162*)(dl + 2 * i) = l;
            }
        } else {
            #pragma unroll
            for (int i = 0; i < 16; i++) {
                *(__nv_bfloat162*)(dh + 2 * i) = __nv_bfloat162(0.f, 0.f);
                *(__nv_bfloat162*)(dl + 2 * i) = __nv_bfloat162(0.f, 0.f);
            }
        }
    }

    // --- B tiles: vectorized copy of pre-converted weights ---
    for (int v = t; v < 1536; v += 256) {
        int m  = v >> 9;
        int rm = v & 511;
        int n  = rm >> 3;
        int k8 = rm & 7;
        int soff = m * 64 * BS + n * BS + k8 * 8;
        *(uint4*)(Bh + soff) = ((const uint4*)g_Wbh)[v];
        *(uint4*)(Bl + soff) = ((const uint4*)g_Wbl)[v];
    }
    __syncthreads();

    // --- A fragments: load once, reuse for all 3 matrices ---
    wmma::fragment<wmma::matrix_a, 16, 16, 16, __nv_bfloat16, wmma::row_major>
        ah[4], al[4];
    #pragma unroll
    for (int k = 0; k < 4; k++) {
        wmma::load_matrix_sync(ah[k], Ah + (w * 16) * AS + k * 16, AS);
        wmma::load_matrix_sync(al[k], Al + (w * 16) * AS + k * 16, AS);
    }

    #pragma unroll
    for (int m = 0; m < 3; m++) {
        const __nv_bfloat16* BH = Bh + m * 64 * BS;
        const __nv_bfloat16* BL = Bl + m * 64 * BS;

        wmma::fragment<wmma::accumulator, 16, 16, 16, float> acc[4];
        #pragma unroll
        for (int n = 0; n < 4; n++) wmma::fill_fragment(acc[n], 0.0f);

        #pragma unroll
        for (int k = 0; k < 4; k++) {
            #pragma unroll
            for (int n = 0; n < 4; n++) {
                wmma::fragment<wmma::matrix_b, 16, 16, 16, __nv_bfloat16,
                               wmma::col_major> bh, bl;
                wmma::load_matrix_sync(bh, BH + (n * 16) * BS + k * 16, BS);
                wmma::load_matrix_sync(bl, BL + (n * 16) * BS + k * 16, BS);
                wmma::mma_sync(acc[n], ah[k], bh, acc[n]);
                wmma::mma_sync(acc[n], ah[k], bl, acc[n]);
                wmma::mma_sync(acc[n], al[k], bh, acc[n]);
            }
        }

        float* O = (m == 0) ? g_Q : (m == 1) ? g_K : g_V;
        #pragma unroll
        for (int n = 0; n < 4; n++)
            wmma::store_matrix_sync(O + (size_t)(base + w * 16) * 64 + n * 16,
                                    acc[n], 64, wmma::mem_row_major);
    }
}

#define SMEM_WMMA ((2 * 128 * AS + 2 * 3 * 64 * BS) * (int)sizeof(__nv_bfloat16))

// ---------------------------------------------------------------------------
// CSR build: histogram -> block scan -> fix (with inline top-prefix) -> scatter
// ---------------------------------------------------------------------------
__global__ void hist_kernel(const int* __restrict__ rows) {
    int e = blockIdx.x * blockDim.x + threadIdx.x;
    if (e < N_EDGES) atomicAdd(&g_deg[rows[e]], 1);
}

__global__ void scan_blocks() {
    int i    = blockIdx.x * 256 + threadIdx.x;
    int lane = threadIdx.x & 31, wid = threadIdx.x >> 5;
    int v = (i < N_NODES) ? g_deg[i] : 0;
    #pragma unroll
    for (int o = 1; o < 32; o <<= 1) {
        int u = __shfl_up_sync(0xffffffffu, v, o);
        if (lane >= o) v += u;
    }
    __shared__ int ws[8];
    if (lane == 31) ws[wid] = v;
    __syncthreads();
    if (wid == 0 && lane < 8) {
        int x = ws[lane];
        #pragma unroll
        for (int o = 1; o < 8; o <<= 1) {
            int u = __shfl_up_sync(0xffu, x, o);
            if (lane >= o) x += u;
        }
        ws[lane] = x;
    }
    __syncthreads();
    if (wid > 0) v += ws[wid - 1];
    g_incl[blockIdx.x * 256 + threadIdx.x] = v;
    if (threadIdx.x == 255) g_bsum[blockIdx.x] = v;
}

// scan_fix with inlined top-level prefix: each block sums bsum[0..blockIdx)
__global__ void scan_fix() {
    __shared__ int s_off;
    __shared__ int ws[8];
    int t = threadIdx.x, lane = t & 31, wid = t >> 5;

    int partial = 0;
    for (int i = t; i < blockIdx.x; i += 256) partial += g_bsum[i];
    #pragma unroll
    for (int o = 16; o > 0; o >>= 1)
        partial += __shfl_down_sync(0xffffffffu, partial, o);
    if (lane == 0) ws[wid] = partial;
    __syncthreads();
    if (t == 0) {
        int tot = 0;
        #pragma unroll
        for (int k = 0; k < 8; k++) tot += ws[k];
        s_off = tot;
    }
    __syncthreads();

    int i = blockIdx.x * 256 + t;
    if (i >= N_NODES) return;
    int st = g_incl[i] + s_off - g_deg[i];
    g_start[i]  = st;
    g_cursor[i] = st;
}

__global__ void scatter_kernel(const int* __restrict__ rows,
                               const int* __restrict__ cols) {
    int e = blockIdx.x * blockDim.x + threadIdx.x;
    if (e >= N_EDGES) return;
    int r = rows[e];
    int p = atomicAdd(&g_cursor[r], 1);
    g_colS[p] = cols[e];
    g_perm[p] = e;
}

// ---------------------------------------------------------------------------
// Warp-per-node fused attention, 8-edge unroll (16 K/V loads in flight).
// 64-thread blocks; lane l owns dims [2l, 2l+1] (head = l>>3).
// ---------------------------------------------------------------------------
__device__ __forceinline__ float dot8(float2 q2, float2 k2) {
    float p = q2.x * k2.x + q2.y * k2.y;
    p += __shfl_xor_sync(0xffffffffu, p, 1);
    p += __shfl_xor_sync(0xffffffffu, p, 2);
    p += __shfl_xor_sync(0xffffffffu, p, 4);
    return __expf(fminf(fmaxf(p, -10.0f), 10.0f));
}

__global__ __launch_bounds__(64) void node_attn(float* __restrict__ res,
                                                float* __restrict__ att) {
    int gwarp = blockIdx.x * 2 + (threadIdx.x >> 5);
    if (gwarp >= N_NODES) return;
    int lane = threadIdx.x & 31;
    int n = gwarp;
    int s = g_start[n];
    int end = s + g_deg[n];

    float2 q2 = *(const float2*)&g_Q[n * DIM + lane * 2];
    float acc0 = 0.f, acc1 = 0.f, norm = 0.f;
    int h = lane >> 3;
    bool leader = (lane & 7) == 0;

    int j = s;
    for (; j + 7 < end; j += 8) {
        int cc[8], ee[8];
        #pragma unroll
        for (int i = 0; i < 8; i++) { cc[i] = g_colS[j + i]; ee[i] = g_perm[j + i]; }
        float2 kk[8], vv[8];
        #pragma unroll
        for (int i = 0; i < 8; i++) {
            kk[i] = *(const float2*)&g_K[cc[i] * DIM + lane * 2];
            vv[i] = *(const float2*)&g_V[cc[i] * DIM + lane * 2];
        }
        float ex[8];
        #pragma unroll
        for (int i = 0; i < 8; i++) ex[i] = dot8(q2, kk[i]);
        #pragma unroll
        for (int i = 0; i < 8; i++) {
            norm += ex[i];
            acc0 = fmaf(ex[i], vv[i].x, acc0);
            acc1 = fmaf(ex[i], vv[i].y, acc1);
            if (leader) att[ee[i] * 4 + h] = ex[i];
        }
    }
    for (; j + 3 < end; j += 4) {
        int cc[4], ee[4];
        #pragma unroll
        for (int i = 0; i < 4; i++) { cc[i] = g_colS[j + i]; ee[i] = g_perm[j + i]; }
        float2 kk[4], vv[4];
        #pragma unroll
        for (int i = 0; i < 4; i++) {
            kk[i] = *(const float2*)&g_K[cc[i] * DIM + lane * 2];
            vv[i] = *(const float2*)&g_V[cc[i] * DIM + lane * 2];
        }
        #pragma unroll
        for (int i = 0; i < 4; i++) {
            float e = dot8(q2, kk[i]);
            norm += e;
            acc0 = fmaf(e, vv[i].x, acc0);
            acc1 = fmaf(e, vv[i].y, acc1);
            if (leader) att[ee[i] * 4 + h] = e;
        }
    }
    for (; j < end; j++) {
        int c = g_colS[j], e0 = g_perm[j];
        float2 k2 = *(const float2*)&g_K[c * DIM + lane * 2];
        float2 v2 = *(const float2*)&g_V[c * DIM + lane * 2];
        float e = dot8(q2, k2);
        norm += e;
        acc0 = fmaf(e, v2.x, acc0);
        acc1 = fmaf(e, v2.y, acc1);
        if (leader) att[e0 * 4 + h] = e;
    }

    float inv = 1.0f / (norm + 1e-8f);
    *(float2*)&res[n * DIM + lane * 2] = make_float2(acc0 * inv, acc1 * inv);

    __syncwarp();
    float i0 = __shfl_sync(0xffffffffu, inv, 0);
    float i1 = __shfl_sync(0xffffffffu, inv, 8);
    float i2 = __shfl_sync(0xffffffffu, inv, 16);
    float i3 = __shfl_sync(0xffffffffu, inv, 24);
    for (int jj = s + lane; jj < end; jj += 32) {
        int e = g_perm[jj];
        float4 a = *(float4*)&att[e * 4];
        a.x *= i0; a.y *= i1; a.z *= i2; a.w *= i3;
        *(float4*)&att[e * 4] = a;
    }
}

// ---------------------------------------------------------------------------
extern "C" void kernel_launch(void* const* d_in, const int* in_sizes, int n_in,
                              void* d_out, int out_size) {
    const float* embeds = (const float*)d_in[0];
    const float* Wq     = (const float*)d_in[1];
    const float* Wk     = (const float*)d_in[2];
    const float* Wv     = (const float*)d_in[3];
    const int*   rows   = (const int*)d_in[4];
    const int*   cols   = (const int*)d_in[5];

    float* res = (float*)d_out;                    // [N_NODES, 64]
    float* att = (float*)d_out + N_NODES * DIM;    // [N_EDGES, 4]

    static cudaStream_t sCsr = nullptr;
    static cudaEvent_t  evFork = nullptr, evJoin = nullptr;
    if (sCsr == nullptr) {
        cudaStreamCreateWithFlags(&sCsr, cudaStreamNonBlocking);
        cudaEventCreateWithFlags(&evFork, cudaEventDisableTiming);
        cudaEventCreateWithFlags(&evJoin, cudaEventDisableTiming);
    }

    void* pDeg;
    cudaGetSymbolAddress(&pDeg, g_deg);

    // Fork: CSR chain (rows/cols only) parallel to tensor-core GEMM.
    cudaEventRecord(evFork, 0);
    cudaStreamWaitEvent(sCsr, evFork, 0);

    // Branch A (stream 0): W pre-convert + wmma QKV projection
    wconv<<<48, 256>>>(Wq, Wk, Wv);
    cudaFuncSetAttribute(gemm_qkv_wmma,
                         cudaFuncAttributeMaxDynamicSharedMemorySize, SMEM_WMMA);
    gemm_qkv_wmma<<<(N_NODES + 127) / 128, 256, SMEM_WMMA>>>(embeds);

    // Branch B (sCsr): CSR build (scan_top folded into scan_fix)
    int eb = (N_EDGES + 255) / 256;
    cudaMemsetAsync(pDeg, 0, (size_t)N_NODES * sizeof(int), sCsr);
    hist_kernel<<<eb, 256, 0, sCsr>>>(rows);
    scan_blocks<<<NBLK, 256, 0, sCsr>>>();
    scan_fix<<<NBLK, 256, 0, sCsr>>>();
    scatter_kernel<<<eb, 256, 0, sCsr>>>(rows, cols);

    // Join
    cudaEventRecord(evJoin, sCsr);
    cudaStreamWaitEvent(0, evJoin, 0);

    // fused attention: logits + softmax + aggregate + att normalize
    node_attn<<<(N_NODES + 1) / 2, 64>>>(res, att);
}

// round 15
// speedup vs baseline: 1.4436x; 1.0043x over previous
#include <cuda_runtime.h>
#include <cuda_bf16.h>
#include <mma.h>

using namespace nvcuda;

#define N_NODES 100000
#define N_PAD   100096                    // 128-aligned for unguarded wmma stores
#define N_EDGES 800000
#define DIM     64
#define HEADS   4
#define NBLK    ((N_NODES + 255) / 256)   // 391 scan blocks

typedef unsigned long long u64;
typedef unsigned int       u32;

// L2-resident scratch (GB300 L2 ~126MB; Q+K+V = 76.9MB)
__device__ float g_Q[N_PAD * DIM];
__device__ float g_K[N_PAD * DIM];
__device__ float g_V[N_PAD * DIM];

// Pre-converted weights: [m][n][k] bf16 (W^T layout), hi / lo split
__device__ __nv_bfloat16 g_Wbh[3 * 64 * 64];
__device__ __nv_bfloat16 g_Wbl[3 * 64 * 64];

// CSR scratch
__device__ int g_deg[N_NODES];
__device__ int g_start[N_NODES];
__device__ int g_cursor[N_NODES];
__device__ int g_incl[NBLK * 256];
__device__ int g_bsum[NBLK];
__device__ int g_colS[N_EDGES];
__device__ int g_perm[N_EDGES];

// ---------------------------------------------------------------------------
// One-shot W transpose + bf16 hi/lo split. 12288 elements.
// ---------------------------------------------------------------------------
__global__ void wconv(const float* __restrict__ Wq, const float* __restrict__ Wk,
                      const float* __restrict__ Wv) {
    int idx = blockIdx.x * 256 + threadIdx.x;
    if (idx >= 3 * 4096) return;
    int m = idx >> 12, rem = idx & 4095;
    int n = rem >> 6, k = rem & 63;
    const float* W = (m == 0) ? Wq : (m == 1) ? Wk : Wv;
    float x = W[k * 64 + n];
    __nv_bfloat16 h = __float2bfloat16_rn(x);
    __nv_bfloat16 l = __float2bfloat16_rn(x - __bfloat162float(h));
    g_Wbh[idx] = h;
    g_Wbl[idx] = l;
}

// ---------------------------------------------------------------------------
// Tensor-core QKV GEMM via wmma (bf16 two-term split, err ~2^-18).
// 256 threads (8 warps), 128-node tile. Pre-converted B matrices staged once
// with uint4 copies; A fragments register-resident; one __syncthreads.
// ---------------------------------------------------------------------------
#define AS 72
#define BS 72

__global__ __launch_bounds__(256, 2) void gemm_qkv_wmma(const float* __restrict__ E)
{
    extern __shared__ __nv_bfloat16 sb[];
    __nv_bfloat16* Ah = sb;                    // [128][AS]
    __nv_bfloat16* Al = Ah + 128 * AS;
    __nv_bfloat16* Bh = Al + 128 * AS;         // [3][64][BS]
    __nv_bfloat16* Bl = Bh + 3 * 64 * BS;

    int t    = threadIdx.x;
    int w    = t >> 5;
    int base = blockIdx.x * 128;

    // --- A tile: each thread converts half a row (32 floats) ---
    {
        int r    = t >> 1;
        int coff = (t & 1) * 32;
        int node = base + r;
        const float2* src = (const float2*)(E + (size_t)node * 64 + coff);
        __nv_bfloat16* dh = Ah + r * AS + coff;
        __nv_bfloat16* dl = Al + r * AS + coff;
        if (node < N_NODES) {
            #pragma unroll
            for (int i = 0; i < 16; i++) {
                float2 x = src[i];
                __nv_bfloat162 h = __float22bfloat162_rn(x);
                float2 hf = __bfloat1622float2(h);
                __nv_bfloat162 l = __float22bfloat162_rn(
                    make_float2(x.x - hf.x, x.y - hf.y));
                *(__nv_bfloat162*)(dh + 2 * i) = h;
                *(__nv_bfloat162*)(dl + 2 * i) = l;
            }
        } else {
            #pragma unroll
            for (int i = 0; i < 16; i++) {
                *(__nv_bfloat162*)(dh + 2 * i) = __nv_bfloat162(0.f, 0.f);
                *(__nv_bfloat162*)(dl + 2 * i) = __nv_bfloat162(0.f, 0.f);
            }
        }
    }

    // --- B tiles: vectorized copy of pre-converted weights ---
    for (int v = t; v < 1536; v += 256) {
        int m  = v >> 9;
        int rm = v & 511;
        int n  = rm >> 3;
        int k8 = rm & 7;
        int soff = m * 64 * BS + n * BS + k8 * 8;
        *(uint4*)(Bh + soff) = ((const uint4*)g_Wbh)[v];
        *(uint4*)(Bl + soff) = ((const uint4*)g_Wbl)[v];
    }
    __syncthreads();

    // --- A fragments: load once, reuse for all 3 matrices ---
    wmma::fragment<wmma::matrix_a, 16, 16, 16, __nv_bfloat16, wmma::row_major>
        ah[4], al[4];
    #pragma unroll
    for (int k = 0; k < 4; k++) {
        wmma::load_matrix_sync(ah[k], Ah + (w * 16) * AS + k * 16, AS);
        wmma::load_matrix_sync(al[k], Al + (w * 16) * AS + k * 16, AS);
    }

    #pragma unroll
    for (int m = 0; m < 3; m++) {
        const __nv_bfloat16* BH = Bh + m * 64 * BS;
        const __nv_bfloat16* BL = Bl + m * 64 * BS;

        wmma::fragment<wmma::accumulator, 16, 16, 16, float> acc[4];
        #pragma unroll
        for (int n = 0; n < 4; n++) wmma::fill_fragment(acc[n], 0.0f);

        #pragma unroll
        for (int k = 0; k < 4; k++) {
            #pragma unroll
            for (int n = 0; n < 4; n++) {
                wmma::fragment<wmma::matrix_b, 16, 16, 16, __nv_bfloat16,
                               wmma::col_major> bh, bl;
                wmma::load_matrix_sync(bh, BH + (n * 16) * BS + k * 16, BS);
                wmma::load_matrix_sync(bl, BL + (n * 16) * BS + k * 16, BS);
                wmma::mma_sync(acc[n], ah[k], bh, acc[n]);
                wmma::mma_sync(acc[n], ah[k], bl, acc[n]);
                wmma::mma_sync(acc[n], al[k], bh, acc[n]);
            }
        }

        float* O = (m == 0) ? g_Q : (m == 1) ? g_K : g_V;
        #pragma unroll
        for (int n = 0; n < 4; n++)
            wmma::store_matrix_sync(O + (size_t)(base + w * 16) * 64 + n * 16,
                                    acc[n], 64, wmma::mem_row_major);
    }
}

#define SMEM_WMMA ((2 * 128 * AS + 2 * 3 * 64 * BS) * (int)sizeof(__nv_bfloat16))

// ---------------------------------------------------------------------------
// CSR build: histogram -> block scan -> fix (with inline top-prefix) -> scatter
// ---------------------------------------------------------------------------
__global__ void hist_kernel(const int* __restrict__ rows) {
    int e = blockIdx.x * blockDim.x + threadIdx.x;
    if (e < N_EDGES) atomicAdd(&g_deg[rows[e]], 1);
}

__global__ void scan_blocks() {
    int i    = blockIdx.x * 256 + threadIdx.x;
    int lane = threadIdx.x & 31, wid = threadIdx.x >> 5;
    int v = (i < N_NODES) ? g_deg[i] : 0;
    #pragma unroll
    for (int o = 1; o < 32; o <<= 1) {
        int u = __shfl_up_sync(0xffffffffu, v, o);
        if (lane >= o) v += u;
    }
    __shared__ int ws[8];
    if (lane == 31) ws[wid] = v;
    __syncthreads();
    if (wid == 0 && lane < 8) {
        int x = ws[lane];
        #pragma unroll
        for (int o = 1; o < 8; o <<= 1) {
            int u = __shfl_up_sync(0xffu, x, o);
            if (lane >= o) x += u;
        }
        ws[lane] = x;
    }
    __syncthreads();
    if (wid > 0) v += ws[wid - 1];
    g_incl[blockIdx.x * 256 + threadIdx.x] = v;
    if (threadIdx.x == 255) g_bsum[blockIdx.x] = v;
}

// scan_fix with inlined top-level prefix: each block sums bsum[0..blockIdx)
__global__ void scan_fix() {
    __shared__ int s_off;
    __shared__ int ws[8];
    int t = threadIdx.x, lane = t & 31, wid = t >> 5;

    int partial = 0;
    for (int i = t; i < blockIdx.x; i += 256) partial += g_bsum[i];
    #pragma unroll
    for (int o = 16; o > 0; o >>= 1)
        partial += __shfl_down_sync(0xffffffffu, partial, o);
    if (lane == 0) ws[wid] = partial;
    __syncthreads();
    if (t == 0) {
        int tot = 0;
        #pragma unroll
        for (int k = 0; k < 8; k++) tot += ws[k];
        s_off = tot;
    }
    __syncthreads();

    int i = blockIdx.x * 256 + t;
    if (i >= N_NODES) return;
    int st = g_incl[i] + s_off - g_deg[i];
    g_start[i]  = st;
    g_cursor[i] = st;
}

__global__ void scatter_kernel(const int* __restrict__ rows,
                               const int* __restrict__ cols) {
    int e = blockIdx.x * blockDim.x + threadIdx.x;
    if (e >= N_EDGES) return;
    int r = rows[e];
    int p = atomicAdd(&g_cursor[r], 1);
    g_colS[p] = cols[e];
    g_perm[p] = e;
}

// ---------------------------------------------------------------------------
// Half-warp-per-node fused attention. 16 lanes per node; lane owns 4 dims
// (head = l>>2, float4 K/V loads, 2-shfl dot). Two nodes per warp advance in
// LOCKSTEP to max(d0,d1) with predication -> 40% fewer issue slots than
// warp-per-node. 4-edge unroll for load MLP.
// ---------------------------------------------------------------------------
__global__ __launch_bounds__(64) void node_attn(float* __restrict__ res,
                                                float* __restrict__ att) {
    int tid  = threadIdx.x;
    int node = blockIdx.x * 4 + (tid >> 4);
    bool vn  = node < N_NODES;
    int n = vn ? node : 0;
    int l = tid & 15;                 // lane within half-warp
    int h = l >> 2;                   // head (4 lanes per head)
    int s = g_start[n];
    int d = vn ? g_deg[n] : 0;
    int dmax = max(d, __shfl_xor_sync(0xffffffffu, d, 16));

    float4 q4 = *(const float4*)&g_Q[(size_t)n * DIM + l * 4];
    float4 acc = make_float4(0.f, 0.f, 0.f, 0.f);
    float norm = 0.f;
    bool leader = (l & 3) == 0;

    for (int j = 0; j < dmax; j += 4) {
        bool va[4];
        int  idx[4], cc[4];
        #pragma unroll
        for (int i = 0; i < 4; i++) {
            va[i]  = (j + i) < d;
            idx[i] = va[i] ? (s + j + i) : 0;      // safe dummy
        }
        #pragma unroll
        for (int i = 0; i < 4; i++) cc[i] = g_colS[idx[i]];
        float4 kk[4], vv[4];
        #pragma unroll
        for (int i = 0; i < 4; i++) {
            kk[i] = *(const float4*)&g_K[(size_t)cc[i] * DIM + l * 4];
            vv[i] = *(const float4*)&g_V[(size_t)cc[i] * DIM + l * 4];
        }
        #pragma unroll
        for (int i = 0; i < 4; i++) {
            float p = kk[i].x * q4.x + kk[i].y * q4.y
                    + kk[i].z * q4.z + kk[i].w * q4.w;
            p += __shfl_xor_sync(0xffffffffu, p, 1);
            p += __shfl_xor_sync(0xffffffffu, p, 2);
            float ex = va[i] ? __expf(fminf(fmaxf(p, -10.f), 10.f)) : 0.f;
            norm += ex;
            acc.x = fmaf(ex, vv[i].x, acc.x);
            acc.y = fmaf(ex, vv[i].y, acc.y);
            acc.z = fmaf(ex, vv[i].z, acc.z);
            acc.w = fmaf(ex, vv[i].w, acc.w);
            if (va[i] && leader) att[g_perm[idx[i]] * 4 + h] = ex;
        }
    }

    float inv = 1.0f / (norm + 1e-8f);
    if (vn)
        *(float4*)&res[(size_t)n * DIM + l * 4] =
            make_float4(acc.x * inv, acc.y * inv, acc.z * inv, acc.w * inv);

    // normalize this node's att entries (16-lane strided per half)
    int hb = tid & 16;                // half base within warp (0 or 16)
    float i0 = __shfl_sync(0xffffffffu, inv, hb + 0);
    float i1 = __shfl_sync(0xffffffffu, inv, hb + 4);
    float i2 = __shfl_sync(0xffffffffu, inv, hb + 8);
    float i3 = __shfl_sync(0xffffffffu, inv, hb + 12);
    for (int jj = l; jj < d; jj += 16) {
        int e = g_perm[s + jj];
        float4 a = *(float4*)&att[e * 4];
        a.x *= i0; a.y *= i1; a.z *= i2; a.w *= i3;
        *(float4*)&att[e * 4] = a;
    }
}

// ---------------------------------------------------------------------------
extern "C" void kernel_launch(void* const* d_in, const int* in_sizes, int n_in,
                              void* d_out, int out_size) {
    const float* embeds = (const float*)d_in[0];
    const float* Wq     = (const float*)d_in[1];
    const float* Wk     = (const float*)d_in[2];
    const float* Wv     = (const float*)d_in[3];
    const int*   rows   = (const int*)d_in[4];
    const int*   cols   = (const int*)d_in[5];

    float* res = (float*)d_out;                    // [N_NODES, 64]
    float* att = (float*)d_out + N_NODES * DIM;    // [N_EDGES, 4]

    static cudaStream_t sCsr = nullptr;
    static cudaEvent_t  evFork = nullptr, evJoin = nullptr;
    if (sCsr == nullptr) {
        cudaStreamCreateWithFlags(&sCsr, cudaStreamNonBlocking);
        cudaEventCreateWithFlags(&evFork, cudaEventDisableTiming);
        cudaEventCreateWithFlags(&evJoin, cudaEventDisableTiming);
    }

    void* pDeg;
    cudaGetSymbolAddress(&pDeg, g_deg);

    // Fork: CSR chain (rows/cols only) parallel to tensor-core GEMM.
    cudaEventRecord(evFork, 0);
    cudaStreamWaitEvent(sCsr, evFork, 0);

    // Branch A (stream 0): W pre-convert + wmma QKV projection
    wconv<<<48, 256>>>(Wq, Wk, Wv);
    cudaFuncSetAttribute(gemm_qkv_wmma,
                         cudaFuncAttributeMaxDynamicSharedMemorySize, SMEM_WMMA);
    gemm_qkv_wmma<<<(N_NODES + 127) / 128, 256, SMEM_WMMA>>>(embeds);

    // Branch B (sCsr): CSR build
    int eb = (N_EDGES + 255) / 256;
    cudaMemsetAsync(pDeg, 0, (size_t)N_NODES * sizeof(int), sCsr);
    hist_kernel<<<eb, 256, 0, sCsr>>>(rows);
    scan_blocks<<<NBLK, 256, 0, sCsr>>>();
    scan_fix<<<NBLK, 256, 0, sCsr>>>();
    scatter_kernel<<<eb, 256, 0, sCsr>>>(rows, cols);

    // Join
    cudaEventRecord(evJoin, sCsr);
    cudaStreamWaitEvent(0, evJoin, 0);

    // fused attention: logits + softmax + aggregate + att normalize
    node_attn<<<(N_NODES + 3) / 4, 64>>>(res, att);
}